// round 2
// baseline (speedup 1.0000x reference)
#include <cuda_runtime.h>
#include <cstdint>

#define N_NODES 50000
#define N_EDGES 800000
#define IN_F 128
#define HID 128
#define OUT_F 64

// ---------------- scratch (device globals: no allocation allowed) ----------
__device__ float g_xw0[(size_t)N_NODES * HID];   // x @ w0
__device__ float g_h[(size_t)N_NODES * HID];     // relu(spmm(x@w0))
__device__ float g_hw1[(size_t)N_NODES * OUT_F]; // h @ w1
__device__ int   g_rowptr[N_NODES + 1];
__device__ int   g_is64;                         // 1 if edge indices are int64

// ---------------- dtype detection -----------------------------------------
// edge_col holds random values in [0, 50000). If the buffer is int64 (LE),
// every odd 32-bit word is 0. If int32, odd words are random column indices
// (P(all zero) ~ 0). OR-reduce the first 4096 odd words.
__global__ void detect_kernel(const unsigned int* __restrict__ ec_words) {
    unsigned int acc = 0;
    for (int i = 0; i < 4096; i++) acc |= ec_words[2 * i + 1];
    g_is64 = (acc == 0) ? 1 : 0;
}

__device__ __forceinline__ long long load_idx(const void* p, int e, int is64) {
    if (is64) return ((const long long*)p)[e];
    return (long long)((const int*)p)[e];
}

// ---------------- CSR row_ptr via binary search (edge_row is sorted) -------
__global__ void rowptr_kernel(const void* __restrict__ edge_row) {
    int i = blockIdx.x * blockDim.x + threadIdx.x;
    if (i > N_NODES) return;
    const int is64 = g_is64;
    int lo = 0, hi = N_EDGES;
    while (lo < hi) {
        int mid = (lo + hi) >> 1;
        if (load_idx(edge_row, mid, is64) < (long long)i) lo = mid + 1;
        else hi = mid;
    }
    g_rowptr[i] = lo;
}

// ---------------- GEMM1: g_xw0 = x[50000,128] @ w0[128,128] ----------------
__global__ void gemm1_kernel(const float* __restrict__ x,
                             const float* __restrict__ w0) {
    __shared__ float ws[64 * HID];   // ws[k][j] = w0[kt+k][j]
    __shared__ float xs[32 * 64];    // xs[r][k] = x[row0+r][kt+k]
    const int j = threadIdx.x;       // output column 0..127
    const int row0 = blockIdx.x * 32;

    float acc[32];
#pragma unroll
    for (int r = 0; r < 32; r++) acc[r] = 0.f;

    for (int kt = 0; kt < IN_F; kt += 64) {
        for (int idx = j; idx < 64 * HID; idx += 128)
            ws[idx] = w0[(kt + (idx >> 7)) * HID + (idx & 127)];
        for (int idx = j; idx < 32 * 64; idx += 128) {
            int r = idx >> 6, k = idx & 63;
            int row = row0 + r;
            xs[idx] = (row < N_NODES) ? x[(size_t)row * IN_F + kt + k] : 0.f;
        }
        __syncthreads();
#pragma unroll
        for (int r = 0; r < 32; r++) {
            float a = 0.f;
#pragma unroll 16
            for (int k = 0; k < 64; k++)
                a += xs[r * 64 + k] * ws[k * HID + j];
            acc[r] += a;
        }
        __syncthreads();
    }
#pragma unroll
    for (int r = 0; r < 32; r++) {
        int row = row0 + r;
        if (row < N_NODES) g_xw0[(size_t)row * HID + j] = acc[r];
    }
}

// ---------------- SpMM1 + ReLU: one warp per node, float4 per lane ---------
__global__ void spmm1_kernel(const void* __restrict__ edge_col,
                             const float* __restrict__ edge_weight) {
    int gwarp = (blockIdx.x * blockDim.x + threadIdx.x) >> 5;
    int lane = threadIdx.x & 31;
    if (gwarp >= N_NODES) return;
    const int is64 = g_is64;
    int beg = g_rowptr[gwarp];
    int end = g_rowptr[gwarp + 1];
    const float4* feat = reinterpret_cast<const float4*>(g_xw0);
    float4 acc = make_float4(0.f, 0.f, 0.f, 0.f);
    for (int e = beg; e < end; e++) {
        float w = __ldg(edge_weight + e);
        int c = (int)load_idx(edge_col, e, is64);
        float4 v = feat[(size_t)c * 32 + lane];
        acc.x += w * v.x; acc.y += w * v.y;
        acc.z += w * v.z; acc.w += w * v.w;
    }
    float4 r;
    r.x = fmaxf(acc.x, 0.f); r.y = fmaxf(acc.y, 0.f);
    r.z = fmaxf(acc.z, 0.f); r.w = fmaxf(acc.w, 0.f);
    reinterpret_cast<float4*>(g_h)[(size_t)gwarp * 32 + lane] = r;
}

// ---------------- GEMM2: g_hw1 = g_h[50000,128] @ w1[128,64] ---------------
__global__ void gemm2_kernel(const float* __restrict__ w1) {
    __shared__ float ws[HID * OUT_F]; // ws[k][j] = w1[k][j]
    __shared__ float xs[2][HID];
    const int tid = threadIdx.x;
    const int j = tid & 63;
    const int rp = tid >> 6;
    const int row0 = blockIdx.x * 64;

    for (int idx = tid; idx < HID * OUT_F; idx += 128) ws[idx] = w1[idx];
    __syncthreads();

    for (int r2 = 0; r2 < 32; r2++) {
        for (int idx = tid; idx < 2 * HID; idx += 128) {
            int p = idx >> 7, k = idx & 127;
            int rr = row0 + r2 * 2 + p;
            xs[p][k] = (rr < N_NODES) ? g_h[(size_t)rr * HID + k] : 0.f;
        }
        __syncthreads();
        float acc = 0.f;
#pragma unroll 16
        for (int k = 0; k < HID; k++)
            acc += xs[rp][k] * ws[k * OUT_F + j];
        int row = row0 + r2 * 2 + rp;
        if (row < N_NODES) g_hw1[(size_t)row * OUT_F + j] = acc;
        __syncthreads();
    }
}

// ---------------- SpMM2: one warp per node, float2 per lane ----------------
__global__ void spmm2_kernel(const void* __restrict__ edge_col,
                             const float* __restrict__ edge_weight,
                             float* __restrict__ out) {
    int gwarp = (blockIdx.x * blockDim.x + threadIdx.x) >> 5;
    int lane = threadIdx.x & 31;
    if (gwarp >= N_NODES) return;
    const int is64 = g_is64;
    int beg = g_rowptr[gwarp];
    int end = g_rowptr[gwarp + 1];
    const float2* feat = reinterpret_cast<const float2*>(g_hw1);
    float2 acc = make_float2(0.f, 0.f);
    for (int e = beg; e < end; e++) {
        float w = __ldg(edge_weight + e);
        int c = (int)load_idx(edge_col, e, is64);
        float2 v = feat[(size_t)c * 32 + lane];
        acc.x += w * v.x; acc.y += w * v.y;
    }
    reinterpret_cast<float2*>(out)[(size_t)gwarp * 32 + lane] = acc;
}

// ---------------- launch ---------------------------------------------------
extern "C" void kernel_launch(void* const* d_in, const int* in_sizes, int n_in,
                              void* d_out, int out_size) {
    const float* x  = (const float*)d_in[0];
    const void*  er = d_in[1];
    const void*  ec = d_in[2];
    const float* ew = (const float*)d_in[3];
    const float* w0 = (const float*)d_in[4];
    const float* w1 = (const float*)d_in[5];
    float* out = (float*)d_out;

    detect_kernel<<<1, 1>>>((const unsigned int*)ec);
    rowptr_kernel<<<(N_NODES + 1 + 255) / 256, 256>>>(er);
    gemm1_kernel<<<(N_NODES + 31) / 32, 128>>>(x, w0);
    spmm1_kernel<<<(N_NODES * 32 + 255) / 256, 256>>>(ec, ew);
    gemm2_kernel<<<(N_NODES + 63) / 64, 128>>>(w1);
    spmm2_kernel<<<(N_NODES * 32 + 255) / 256, 256>>>(ec, ew, out);
}

// round 3
// speedup vs baseline: 2.2805x; 2.2805x over previous
#include <cuda_runtime.h>
#include <cstdint>

#define N_NODES 50000
#define N_EDGES 800000
#define IN_F 128
#define HID 128
#define OUT_F 64

// ---------------- scratch (device globals: no allocation allowed) ----------
__device__ float g_xw0[(size_t)N_NODES * HID];   // x @ w0
__device__ float g_h[(size_t)N_NODES * HID];     // relu(spmm(x@w0))
__device__ float g_hw1[(size_t)N_NODES * OUT_F]; // h @ w1
__device__ int   g_rowptr[N_NODES + 1];
__device__ int   g_is64;                         // 1 if edge indices are int64

// ---------------- dtype detection (parallel) --------------------------------
// edge_col holds random values in [0, 50000). If the buffer is int64 (LE),
// every odd 32-bit word is 0. If int32, odd words are random nonzero indices.
__global__ void detect_kernel(const unsigned int* __restrict__ ec_words) {
    __shared__ unsigned int red[8];
    unsigned int acc = 0;
    for (int i = threadIdx.x; i < 4096; i += 256) acc |= ec_words[2 * i + 1];
#pragma unroll
    for (int o = 16; o; o >>= 1) acc |= __shfl_xor_sync(0xffffffffu, acc, o);
    if ((threadIdx.x & 31) == 0) red[threadIdx.x >> 5] = acc;
    __syncthreads();
    if (threadIdx.x == 0) {
        unsigned int a = 0;
#pragma unroll
        for (int i = 0; i < 8; i++) a |= red[i];
        g_is64 = (a == 0) ? 1 : 0;
    }
}

__device__ __forceinline__ long long load_idx(const void* p, int e, int is64) {
    if (is64) return ((const long long*)p)[e];
    return (long long)((const int*)p)[e];
}

// ---------------- CSR row_ptr via binary search (edge_row is sorted) -------
__global__ void rowptr_kernel(const void* __restrict__ edge_row) {
    int i = blockIdx.x * blockDim.x + threadIdx.x;
    if (i > N_NODES) return;
    const int is64 = g_is64;
    int lo = 0, hi = N_EDGES;
    while (lo < hi) {
        int mid = (lo + hi) >> 1;
        if (load_idx(edge_row, mid, is64) < (long long)i) lo = mid + 1;
        else hi = mid;
    }
    g_rowptr[i] = lo;
}

// ---------------- GEMM1: g_xw0 = x[50000,128] @ w0[128,128] ----------------
// CTA: 128 rows x 128 cols, 256 threads, 8x8 micro-tile per thread.
// K tiled by 16. As stored k-major: As[k][row]; Bs[k][col].
#define G1_KT 16
__global__ __launch_bounds__(256, 2) void gemm1_kernel(
        const float* __restrict__ x, const float* __restrict__ w0) {
    __shared__ float As[G1_KT][128];
    __shared__ float Bs[G1_KT][128];
    const int tid = threadIdx.x;
    const int tx = tid & 15;          // 16 col-groups of 8
    const int ty = tid >> 4;          // 16 row-groups of 8
    const int row0 = blockIdx.x * 128;

    float acc[8][8];
#pragma unroll
    for (int i = 0; i < 8; i++)
#pragma unroll
        for (int j = 0; j < 8; j++) acc[i][j] = 0.f;

    for (int kt = 0; kt < IN_F; kt += G1_KT) {
        // load A tile transposed: 512 float4 slots, 2 per thread
#pragma unroll
        for (int s = tid; s < 512; s += 256) {
            int r = s >> 2, kq = s & 3;
            int row = row0 + r;
            float4 v = make_float4(0.f, 0.f, 0.f, 0.f);
            if (row < N_NODES)
                v = *reinterpret_cast<const float4*>(x + (size_t)row * IN_F + kt + kq * 4);
            As[kq * 4 + 0][r] = v.x;
            As[kq * 4 + 1][r] = v.y;
            As[kq * 4 + 2][r] = v.z;
            As[kq * 4 + 3][r] = v.w;
        }
        // load B tile: 16 k-rows x 128 cols = 512 float4, 2 per thread
#pragma unroll
        for (int s = tid; s < 512; s += 256) {
            int k = s >> 5, cq = s & 31;
            *reinterpret_cast<float4*>(&Bs[k][cq * 4]) =
                *reinterpret_cast<const float4*>(w0 + (size_t)(kt + k) * HID + cq * 4);
        }
        __syncthreads();
#pragma unroll
        for (int k = 0; k < G1_KT; k++) {
            float4 a0 = *reinterpret_cast<const float4*>(&As[k][ty * 8]);
            float4 a1 = *reinterpret_cast<const float4*>(&As[k][ty * 8 + 4]);
            float4 b0 = *reinterpret_cast<const float4*>(&Bs[k][tx * 8]);
            float4 b1 = *reinterpret_cast<const float4*>(&Bs[k][tx * 8 + 4]);
            float av[8] = {a0.x, a0.y, a0.z, a0.w, a1.x, a1.y, a1.z, a1.w};
            float bv[8] = {b0.x, b0.y, b0.z, b0.w, b1.x, b1.y, b1.z, b1.w};
#pragma unroll
            for (int i = 0; i < 8; i++)
#pragma unroll
                for (int j = 0; j < 8; j++)
                    acc[i][j] += av[i] * bv[j];
        }
        __syncthreads();
    }
#pragma unroll
    for (int i = 0; i < 8; i++) {
        int row = row0 + ty * 8 + i;
        if (row < N_NODES) {
            float4 o0 = make_float4(acc[i][0], acc[i][1], acc[i][2], acc[i][3]);
            float4 o1 = make_float4(acc[i][4], acc[i][5], acc[i][6], acc[i][7]);
            *reinterpret_cast<float4*>(g_xw0 + (size_t)row * HID + tx * 8) = o0;
            *reinterpret_cast<float4*>(g_xw0 + (size_t)row * HID + tx * 8 + 4) = o1;
        }
    }
}

// ---------------- SpMM1 + ReLU: one warp per node, float4 per lane ---------
__global__ void spmm1_kernel(const void* __restrict__ edge_col,
                             const float* __restrict__ edge_weight) {
    int gwarp = (blockIdx.x * blockDim.x + threadIdx.x) >> 5;
    int lane = threadIdx.x & 31;
    if (gwarp >= N_NODES) return;
    const int is64 = g_is64;
    int beg = g_rowptr[gwarp];
    int end = g_rowptr[gwarp + 1];
    const float4* feat = reinterpret_cast<const float4*>(g_xw0);
    float4 acc = make_float4(0.f, 0.f, 0.f, 0.f);
    for (int e = beg; e < end; e++) {
        float w = __ldg(edge_weight + e);
        int c = (int)load_idx(edge_col, e, is64);
        float4 v = feat[(size_t)c * 32 + lane];
        acc.x += w * v.x; acc.y += w * v.y;
        acc.z += w * v.z; acc.w += w * v.w;
    }
    float4 r;
    r.x = fmaxf(acc.x, 0.f); r.y = fmaxf(acc.y, 0.f);
    r.z = fmaxf(acc.z, 0.f); r.w = fmaxf(acc.w, 0.f);
    reinterpret_cast<float4*>(g_h)[(size_t)gwarp * 32 + lane] = r;
}

// ---------------- GEMM2: g_hw1 = g_h[50000,128] @ w1[128,64] ---------------
// CTA: 128 rows x 64 cols, 256 threads, 4x8 micro-tile. K tiled by 16.
#define G2_KT 16
__global__ __launch_bounds__(256, 2) void gemm2_kernel(const float* __restrict__ w1) {
    __shared__ float As[G2_KT][128];
    __shared__ float Bs[G2_KT][64];
    const int tid = threadIdx.x;
    const int tx = tid & 7;           // 8 col-groups of 8
    const int ty = tid >> 3;          // 32 row-groups of 4
    const int row0 = blockIdx.x * 128;

    float acc[4][8];
#pragma unroll
    for (int i = 0; i < 4; i++)
#pragma unroll
        for (int j = 0; j < 8; j++) acc[i][j] = 0.f;

    for (int kt = 0; kt < HID; kt += G2_KT) {
        // A tile transposed: 512 float4 slots, 2 per thread
#pragma unroll
        for (int s = tid; s < 512; s += 256) {
            int r = s >> 2, kq = s & 3;
            int row = row0 + r;
            float4 v = make_float4(0.f, 0.f, 0.f, 0.f);
            if (row < N_NODES)
                v = *reinterpret_cast<const float4*>(g_h + (size_t)row * HID + kt + kq * 4);
            As[kq * 4 + 0][r] = v.x;
            As[kq * 4 + 1][r] = v.y;
            As[kq * 4 + 2][r] = v.z;
            As[kq * 4 + 3][r] = v.w;
        }
        // B tile: 16 x 64 = 256 float4 slots, 1 per thread
        {
            int s = tid;
            int k = s >> 4, cq = s & 15;
            *reinterpret_cast<float4*>(&Bs[k][cq * 4]) =
                *reinterpret_cast<const float4*>(w1 + (size_t)(kt + k) * OUT_F + cq * 4);
        }
        __syncthreads();
#pragma unroll
        for (int k = 0; k < G2_KT; k++) {
            float4 a0 = *reinterpret_cast<const float4*>(&As[k][ty * 4]);
            float4 b0 = *reinterpret_cast<const float4*>(&Bs[k][tx * 8]);
            float4 b1 = *reinterpret_cast<const float4*>(&Bs[k][tx * 8 + 4]);
            float av[4] = {a0.x, a0.y, a0.z, a0.w};
            float bv[8] = {b0.x, b0.y, b0.z, b0.w, b1.x, b1.y, b1.z, b1.w};
#pragma unroll
            for (int i = 0; i < 4; i++)
#pragma unroll
                for (int j = 0; j < 8; j++)
                    acc[i][j] += av[i] * bv[j];
        }
        __syncthreads();
    }
#pragma unroll
    for (int i = 0; i < 4; i++) {
        int row = row0 + ty * 4 + i;
        if (row < N_NODES) {
            float4 o0 = make_float4(acc[i][0], acc[i][1], acc[i][2], acc[i][3]);
            float4 o1 = make_float4(acc[i][4], acc[i][5], acc[i][6], acc[i][7]);
            *reinterpret_cast<float4*>(g_hw1 + (size_t)row * OUT_F + tx * 8) = o0;
            *reinterpret_cast<float4*>(g_hw1 + (size_t)row * OUT_F + tx * 8 + 4) = o1;
        }
    }
}

// ---------------- SpMM2: one warp per node, float2 per lane ----------------
__global__ void spmm2_kernel(const void* __restrict__ edge_col,
                             const float* __restrict__ edge_weight,
                             float* __restrict__ out) {
    int gwarp = (blockIdx.x * blockDim.x + threadIdx.x) >> 5;
    int lane = threadIdx.x & 31;
    if (gwarp >= N_NODES) return;
    const int is64 = g_is64;
    int beg = g_rowptr[gwarp];
    int end = g_rowptr[gwarp + 1];
    const float2* feat = reinterpret_cast<const float2*>(g_hw1);
    float2 acc = make_float2(0.f, 0.f);
    for (int e = beg; e < end; e++) {
        float w = __ldg(edge_weight + e);
        int c = (int)load_idx(edge_col, e, is64);
        float2 v = feat[(size_t)c * 32 + lane];
        acc.x += w * v.x; acc.y += w * v.y;
    }
    reinterpret_cast<float2*>(out)[(size_t)gwarp * 32 + lane] = acc;
}

// ---------------- launch ---------------------------------------------------
extern "C" void kernel_launch(void* const* d_in, const int* in_sizes, int n_in,
                              void* d_out, int out_size) {
    const float* x  = (const float*)d_in[0];
    const void*  er = d_in[1];
    const void*  ec = d_in[2];
    const float* ew = (const float*)d_in[3];
    const float* w0 = (const float*)d_in[4];
    const float* w1 = (const float*)d_in[5];
    float* out = (float*)d_out;

    detect_kernel<<<1, 256>>>((const unsigned int*)ec);
    rowptr_kernel<<<(N_NODES + 1 + 255) / 256, 256>>>(er);
    gemm1_kernel<<<(N_NODES + 127) / 128, 256>>>(x, w0);
    spmm1_kernel<<<(N_NODES * 32 + 255) / 256, 256>>>(ec, ew);
    gemm2_kernel<<<(N_NODES + 127) / 128, 256>>>(w1);
    spmm2_kernel<<<(N_NODES * 32 + 255) / 256, 256>>>(ec, ew, out);
}

// round 12
// speedup vs baseline: 2.4182x; 1.0604x over previous
#include <cuda_runtime.h>
#include <cstdint>

#define N_NODES 50000
#define N_EDGES 800000
#define IN_F 128
#define HID 128
#define OUT_F 64

// ---------------- scratch (device globals: no allocation allowed) ----------
__device__ float g_xw0[(size_t)N_NODES * HID];   // x @ w0
__device__ float g_h[(size_t)N_NODES * HID];     // relu(spmm(x@w0))
__device__ float g_hw1[(size_t)N_NODES * OUT_F]; // h @ w1
__device__ int   g_rowptr[N_NODES + 1];
__device__ int   g_is64;                         // 1 if edge indices are int64

// ---------------- dtype detection (parallel) --------------------------------
__global__ void detect_kernel(const unsigned int* __restrict__ ec_words) {
    __shared__ unsigned int red[8];
    unsigned int acc = 0;
    for (int i = threadIdx.x; i < 4096; i += 256) acc |= ec_words[2 * i + 1];
#pragma unroll
    for (int o = 16; o; o >>= 1) acc |= __shfl_xor_sync(0xffffffffu, acc, o);
    if ((threadIdx.x & 31) == 0) red[threadIdx.x >> 5] = acc;
    __syncthreads();
    if (threadIdx.x == 0) {
        unsigned int a = 0;
#pragma unroll
        for (int i = 0; i < 8; i++) a |= red[i];
        g_is64 = (a == 0) ? 1 : 0;
    }
}

__device__ __forceinline__ long long load_idx(const void* p, int e, int is64) {
    if (is64) return ((const long long*)p)[e];
    return (long long)((const int*)p)[e];
}

// ---------------- CSR row_ptr via binary search (edge_row is sorted) -------
__global__ void rowptr_kernel(const void* __restrict__ edge_row) {
    int i = blockIdx.x * blockDim.x + threadIdx.x;
    if (i > N_NODES) return;
    const int is64 = g_is64;
    int lo = 0, hi = N_EDGES;
    while (lo < hi) {
        int mid = (lo + hi) >> 1;
        if (load_idx(edge_row, mid, is64) < (long long)i) lo = mid + 1;
        else hi = mid;
    }
    g_rowptr[i] = lo;
}

// ---------------- GEMM1: g_xw0 = x[50000,128] @ w0[128,128] ----------------
// CTA: 128 rows x 128 cols, 256 threads, 8x8 micro-tile per thread.
// K tiled by 32. As stored k-major: As[k][row]; Bs[k][col].
#define G1_KT 32
__global__ __launch_bounds__(256, 2) void gemm1_kernel(
        const float* __restrict__ x, const float* __restrict__ w0) {
    __shared__ float As[G1_KT][128];   // 16 KB
    __shared__ float Bs[G1_KT][128];   // 16 KB
    const int tid = threadIdx.x;
    const int tx = tid & 15;          // 16 col-groups of 8
    const int ty = tid >> 4;          // 16 row-groups of 8
    const int row0 = blockIdx.x * 128;

    float acc[8][8];
#pragma unroll
    for (int i = 0; i < 8; i++)
#pragma unroll
        for (int j = 0; j < 8; j++) acc[i][j] = 0.f;

    for (int kt = 0; kt < IN_F; kt += G1_KT) {
        // A tile transposed: 128 rows x 8 kq = 1024 float4 slots, 4/thread
#pragma unroll
        for (int s = tid; s < 1024; s += 256) {
            int r = s >> 3, kq = s & 7;
            int row = row0 + r;
            float4 v = make_float4(0.f, 0.f, 0.f, 0.f);
            if (row < N_NODES)
                v = *reinterpret_cast<const float4*>(x + (size_t)row * IN_F + kt + kq * 4);
            As[kq * 4 + 0][r] = v.x;
            As[kq * 4 + 1][r] = v.y;
            As[kq * 4 + 2][r] = v.z;
            As[kq * 4 + 3][r] = v.w;
        }
        // B tile: 32 k-rows x 128 cols = 1024 float4 slots, 4/thread
#pragma unroll
        for (int s = tid; s < 1024; s += 256) {
            int k = s >> 5, cq = s & 31;
            *reinterpret_cast<float4*>(&Bs[k][cq * 4]) =
                *reinterpret_cast<const float4*>(w0 + (size_t)(kt + k) * HID + cq * 4);
        }
        __syncthreads();
#pragma unroll
        for (int k = 0; k < G1_KT; k++) {
            float4 a0 = *reinterpret_cast<const float4*>(&As[k][ty * 8]);
            float4 a1 = *reinterpret_cast<const float4*>(&As[k][ty * 8 + 4]);
            float4 b0 = *reinterpret_cast<const float4*>(&Bs[k][tx * 8]);
            float4 b1 = *reinterpret_cast<const float4*>(&Bs[k][tx * 8 + 4]);
            float av[8] = {a0.x, a0.y, a0.z, a0.w, a1.x, a1.y, a1.z, a1.w};
            float bv[8] = {b0.x, b0.y, b0.z, b0.w, b1.x, b1.y, b1.z, b1.w};
#pragma unroll
            for (int i = 0; i < 8; i++)
#pragma unroll
                for (int j = 0; j < 8; j++)
                    acc[i][j] += av[i] * bv[j];
        }
        __syncthreads();
    }
#pragma unroll
    for (int i = 0; i < 8; i++) {
        int row = row0 + ty * 8 + i;
        if (row < N_NODES) {
            float4 o0 = make_float4(acc[i][0], acc[i][1], acc[i][2], acc[i][3]);
            float4 o1 = make_float4(acc[i][4], acc[i][5], acc[i][6], acc[i][7]);
            *reinterpret_cast<float4*>(g_xw0 + (size_t)row * HID + tx * 8) = o0;
            *reinterpret_cast<float4*>(g_xw0 + (size_t)row * HID + tx * 8 + 4) = o1;
        }
    }
}

// ---------------- SpMM1 + ReLU: one warp per node, float4 per lane ---------
__global__ void spmm1_kernel(const void* __restrict__ edge_col,
                             const float* __restrict__ edge_weight) {
    int gwarp = (blockIdx.x * blockDim.x + threadIdx.x) >> 5;
    int lane = threadIdx.x & 31;
    if (gwarp >= N_NODES) return;
    const int is64 = g_is64;
    int beg = g_rowptr[gwarp];
    int end = g_rowptr[gwarp + 1];
    const float4* feat = reinterpret_cast<const float4*>(g_xw0);
    float4 acc = make_float4(0.f, 0.f, 0.f, 0.f);
    for (int e = beg; e < end; e++) {
        float w = __ldg(edge_weight + e);
        int c = (int)load_idx(edge_col, e, is64);
        float4 v = feat[(size_t)c * 32 + lane];
        acc.x += w * v.x; acc.y += w * v.y;
        acc.z += w * v.z; acc.w += w * v.w;
    }
    float4 r;
    r.x = fmaxf(acc.x, 0.f); r.y = fmaxf(acc.y, 0.f);
    r.z = fmaxf(acc.z, 0.f); r.w = fmaxf(acc.w, 0.f);
    reinterpret_cast<float4*>(g_h)[(size_t)gwarp * 32 + lane] = r;
}

// ---------------- GEMM2: g_hw1 = g_h[50000,128] @ w1[128,64] ---------------
// CTA: 128 rows x 64 cols, 256 threads, 4x8 micro-tile. K tiled by 32.
#define G2_KT 32
__global__ __launch_bounds__(256, 2) void gemm2_kernel(const float* __restrict__ w1) {
    __shared__ float As[G2_KT][128];   // 16 KB
    __shared__ float Bs[G2_KT][64];    //  8 KB
    const int tid = threadIdx.x;
    const int tx = tid & 7;           // 8 col-groups of 8
    const int ty = tid >> 3;          // 32 row-groups of 4
    const int row0 = blockIdx.x * 128;

    float acc[4][8];
#pragma unroll
    for (int i = 0; i < 4; i++)
#pragma unroll
        for (int j = 0; j < 8; j++) acc[i][j] = 0.f;

    for (int kt = 0; kt < HID; kt += G2_KT) {
        // A tile transposed: 1024 float4 slots, 4/thread
#pragma unroll
        for (int s = tid; s < 1024; s += 256) {
            int r = s >> 3, kq = s & 7;
            int row = row0 + r;
            float4 v = make_float4(0.f, 0.f, 0.f, 0.f);
            if (row < N_NODES)
                v = *reinterpret_cast<const float4*>(g_h + (size_t)row * HID + kt + kq * 4);
            As[kq * 4 + 0][r] = v.x;
            As[kq * 4 + 1][r] = v.y;
            As[kq * 4 + 2][r] = v.z;
            As[kq * 4 + 3][r] = v.w;
        }
        // B tile: 32 k x 16 cq = 512 float4 slots, 2/thread
#pragma unroll
        for (int s = tid; s < 512; s += 256) {
            int k = s >> 4, cq = s & 15;
            *reinterpret_cast<float4*>(&Bs[k][cq * 4]) =
                *reinterpret_cast<const float4*>(w1 + (size_t)(kt + k) * OUT_F + cq * 4);
        }
        __syncthreads();
#pragma unroll
        for (int k = 0; k < G2_KT; k++) {
            float4 a0 = *reinterpret_cast<const float4*>(&As[k][ty * 4]);
            float4 b0 = *reinterpret_cast<const float4*>(&Bs[k][tx * 8]);
            float4 b1 = *reinterpret_cast<const float4*>(&Bs[k][tx * 8 + 4]);
            float av[4] = {a0.x, a0.y, a0.z, a0.w};
            float bv[8] = {b0.x, b0.y, b0.z, b0.w, b1.x, b1.y, b1.z, b1.w};
#pragma unroll
            for (int i = 0; i < 4; i++)
#pragma unroll
                for (int j = 0; j < 8; j++)
                    acc[i][j] += av[i] * bv[j];
        }
        __syncthreads();
    }
#pragma unroll
    for (int i = 0; i < 4; i++) {
        int row = row0 + ty * 4 + i;
        if (row < N_NODES) {
            float4 o0 = make_float4(acc[i][0], acc[i][1], acc[i][2], acc[i][3]);
            float4 o1 = make_float4(acc[i][4], acc[i][5], acc[i][6], acc[i][7]);
            *reinterpret_cast<float4*>(g_hw1 + (size_t)row * OUT_F + tx * 8) = o0;
            *reinterpret_cast<float4*>(g_hw1 + (size_t)row * OUT_F + tx * 8 + 4) = o1;
        }
    }
}

// ---------------- SpMM2: one warp per node, float2 per lane ----------------
__global__ void spmm2_kernel(const void* __restrict__ edge_col,
                             const float* __restrict__ edge_weight,
                             float* __restrict__ out) {
    int gwarp = (blockIdx.x * blockDim.x + threadIdx.x) >> 5;
    int lane = threadIdx.x & 31;
    if (gwarp >= N_NODES) return;
    const int is64 = g_is64;
    int beg = g_rowptr[gwarp];
    int end = g_rowptr[gwarp + 1];
    const float2* feat = reinterpret_cast<const float2*>(g_hw1);
    float2 acc = make_float2(0.f, 0.f);
    for (int e = beg; e < end; e++) {
        float w = __ldg(edge_weight + e);
        int c = (int)load_idx(edge_col, e, is64);
        float2 v = feat[(size_t)c * 32 + lane];
        acc.x += w * v.x; acc.y += w * v.y;
    }
    reinterpret_cast<float2*>(out)[(size_t)gwarp * 32 + lane] = acc;
}

// ---------------- launch ---------------------------------------------------
extern "C" void kernel_launch(void* const* d_in, const int* in_sizes, int n_in,
                              void* d_out, int out_size) {
    const float* x  = (const float*)d_in[0];
    const void*  er = d_in[1];
    const void*  ec = d_in[2];
    const float* ew = (const float*)d_in[3];
    const float* w0 = (const float*)d_in[4];
    const float* w1 = (const float*)d_in[5];
    float* out = (float*)d_out;

    detect_kernel<<<1, 256>>>((const unsigned int*)ec);
    rowptr_kernel<<<(N_NODES + 1 + 255) / 256, 256>>>(er);
    gemm1_kernel<<<(N_NODES + 127) / 128, 256>>>(x, w0);
    spmm1_kernel<<<(N_NODES * 32 + 255) / 256, 256>>>(ec, ew);
    gemm2_kernel<<<(N_NODES + 127) / 128, 256>>>(w1);
    spmm2_kernel<<<(N_NODES * 32 + 255) / 256, 256>>>(ec, ew, out);
}